// round 1
// baseline (speedup 1.0000x reference)
#include <cuda_runtime.h>
#include <cuda_bf16.h>
#include <math.h>

// Problem constants
#define BB   2
#define LL   4096
#define EE   512
#define HH   8
#define DD   64
#define WIN  128

#define NTOK (BB*LL)          // 8192 tokens
#define QKVN (3*EE)           // 1536

// ---------------------------------------------------------------------------
// Device scratch (static; no runtime allocation allowed)
// Layout: Q,K,V as [B,H,L,D]; O (attention output) as [B,L,H*D]
// ---------------------------------------------------------------------------
__device__ float g_Q[BB*HH*LL*DD];
__device__ float g_K[BB*HH*LL*DD];
__device__ float g_V[BB*HH*LL*DD];
__device__ float g_O[BB*LL*EE];

// ---------------------------------------------------------------------------
// Kernel 1: QKV projection GEMM
//   qkv[i,f] = sum_e x[i,e]*W[f,e] + b[f]   (i in [0,8192), f in [0,1536))
//   Scatter into g_Q/g_K/g_V with [B,H,L,D] layout. Q gets *1/sqrt(D).
//   Tile: 64x64, BK=16, 256 threads, 4x4 micro-tile per thread.
// ---------------------------------------------------------------------------
__global__ __launch_bounds__(256) void qkv_gemm(
    const float* __restrict__ x,      // [8192,512]
    const float* __restrict__ w,      // [1536,512]
    const float* __restrict__ bias)   // [1536]
{
    __shared__ float As[16][64];   // x tile transposed: As[k][m]
    __shared__ float Bs[16][64];   // w tile transposed: Bs[k][n] = w[n0+n][k0+k]

    const int bn = blockIdx.x;     // 0..23  (N/64)
    const int bm = blockIdx.y;     // 0..127 (M/64)
    const int tid = threadIdx.x;
    const int tx = tid & 15;
    const int ty = tid >> 4;
    const int m0 = bm * 64;
    const int n0 = bn * 64;

    float acc[4][4];
    #pragma unroll
    for (int i = 0; i < 4; i++)
        #pragma unroll
        for (int j = 0; j < 4; j++) acc[i][j] = 0.f;

    const int lm = tid >> 2;           // 0..63
    const int lk = (tid & 3) * 4;      // 0,4,8,12

    for (int k0 = 0; k0 < EE; k0 += 16) {
        float4 av = *reinterpret_cast<const float4*>(&x[(size_t)(m0 + lm) * EE + k0 + lk]);
        float4 bv = *reinterpret_cast<const float4*>(&w[(size_t)(n0 + lm) * EE + k0 + lk]);
        As[lk + 0][lm] = av.x; As[lk + 1][lm] = av.y;
        As[lk + 2][lm] = av.z; As[lk + 3][lm] = av.w;
        Bs[lk + 0][lm] = bv.x; Bs[lk + 1][lm] = bv.y;
        Bs[lk + 2][lm] = bv.z; Bs[lk + 3][lm] = bv.w;
        __syncthreads();

        #pragma unroll
        for (int k = 0; k < 16; k++) {
            float4 a = *reinterpret_cast<const float4*>(&As[k][ty * 4]);
            float4 b = *reinterpret_cast<const float4*>(&Bs[k][tx * 4]);
            float ar[4] = {a.x, a.y, a.z, a.w};
            float br[4] = {b.x, b.y, b.z, b.w};
            #pragma unroll
            for (int i = 0; i < 4; i++)
                #pragma unroll
                for (int j = 0; j < 4; j++)
                    acc[i][j] += ar[i] * br[j];
        }
        __syncthreads();
    }

    // Epilogue: this block's 64 output columns lie entirely inside one
    // (sel, head) stripe since n0 is a multiple of 64.
    const int sel = bn >> 3;           // 0=Q 1=K 2=V
    const int h   = bn & 7;
    float* dst = (sel == 0) ? g_Q : (sel == 1) ? g_K : g_V;
    const float scale = (sel == 0) ? 0.125f : 1.0f;   // 1/sqrt(64)

    float bsv[4];
    #pragma unroll
    for (int j = 0; j < 4; j++) bsv[j] = bias[n0 + tx * 4 + j];

    #pragma unroll
    for (int i = 0; i < 4; i++) {
        int row = m0 + ty * 4 + i;            // token index
        int bat = row >> 12;                  // / 4096
        int l   = row & (LL - 1);
        float4 o;
        o.x = (acc[i][0] + bsv[0]) * scale;
        o.y = (acc[i][1] + bsv[1]) * scale;
        o.z = (acc[i][2] + bsv[2]) * scale;
        o.w = (acc[i][3] + bsv[3]) * scale;
        size_t off = (((size_t)(bat * HH + h) * LL) + l) * DD + tx * 4;
        *reinterpret_cast<float4*>(&dst[off]) = o;
    }
}

// ---------------------------------------------------------------------------
// Kernel 2: banded flash attention
//   One block per (b, h, 64-query tile). Keys: window [q0-128, q0+191],
//   processed in 10 chunks of 32 keys. Mask: allowed iff 0 < |q-k| <= 128.
// ---------------------------------------------------------------------------
__global__ __launch_bounds__(256) void attn_kernel()
{
    __shared__ float Qs[64][64];     // [d][m]
    __shared__ float Ks[64][32];     // [d][j]
    __shared__ float Vs[32][64];     // [j][d]
    __shared__ float Ps[64][33];     // scores / probs (padded)
    __shared__ float rowm[64], rowl[64], rowa[64];

    const int q0 = blockIdx.x * 64;
    const int h  = blockIdx.y;
    const int b  = blockIdx.z;
    const int tid = threadIdx.x;
    const int tx = tid & 15;
    const int ty = tid >> 4;

    const size_t head_off = ((size_t)(b * HH + h) * LL) * DD;
    const float* Qg = g_Q + head_off;
    const float* Kg = g_K + head_off;
    const float* Vg = g_V + head_off;

    // Load Q tile transposed into smem (one-time)
    #pragma unroll
    for (int it = 0; it < 16; it++) {
        int idx = tid + it * 256;     // 0..4095
        int r = idx >> 6, d = idx & 63;
        Qs[d][r] = Qg[(size_t)(q0 + r) * DD + d];
    }
    if (tid < 64) { rowm[tid] = -1e30f; rowl[tid] = 0.f; }

    float oacc[4][4];
    #pragma unroll
    for (int i = 0; i < 4; i++)
        #pragma unroll
        for (int j = 0; j < 4; j++) oacc[i][j] = 0.f;

    __syncthreads();

    const int kstart = q0 - WIN;      // multiple of 32 (may be negative)

    for (int c = 0; c < 10; c++) {
        int kc = kstart + c * 32;
        if (kc + 32 <= 0 || kc >= LL) continue;   // uniform branch

        // --- load K chunk (transposed) and V chunk ---
        {
            int dd = (tid & 15) * 4;
            #pragma unroll
            for (int p = 0; p < 2; p++) {
                int j = (tid >> 4) + p * 16;
                int key = kc + j;
                int kk = min(max(key, 0), LL - 1);    // always in range here
                float4 kv = *reinterpret_cast<const float4*>(&Kg[(size_t)kk * DD + dd]);
                Ks[dd + 0][j] = kv.x; Ks[dd + 1][j] = kv.y;
                Ks[dd + 2][j] = kv.z; Ks[dd + 3][j] = kv.w;
                float4 vv = *reinterpret_cast<const float4*>(&Vg[(size_t)kk * DD + dd]);
                *reinterpret_cast<float4*>(&Vs[j][dd]) = vv;
            }
        }
        __syncthreads();

        // --- scores S[64][32]: thread (ty,tx) -> rows 4ty..4ty+3, cols 2tx..2tx+1
        {
            float s[4][2];
            #pragma unroll
            for (int i = 0; i < 4; i++) { s[i][0] = 0.f; s[i][1] = 0.f; }
            #pragma unroll
            for (int d = 0; d < 64; d++) {
                float4 a = *reinterpret_cast<const float4*>(&Qs[d][ty * 4]);
                float ar[4] = {a.x, a.y, a.z, a.w};
                float b0 = Ks[d][tx * 2];
                float b1 = Ks[d][tx * 2 + 1];
                #pragma unroll
                for (int i = 0; i < 4; i++) {
                    s[i][0] += ar[i] * b0;
                    s[i][1] += ar[i] * b1;
                }
            }
            #pragma unroll
            for (int i = 0; i < 4; i++) {
                Ps[ty * 4 + i][tx * 2 + 0] = s[i][0];
                Ps[ty * 4 + i][tx * 2 + 1] = s[i][1];
            }
        }
        __syncthreads();

        // --- online softmax over this chunk (one thread per query row) ---
        if (tid < 64) {
            int r = tid;
            int q = q0 + r;
            float mold = rowm[r];
            float mx = mold;
            #pragma unroll
            for (int j = 0; j < 32; j++) {
                int key = kc + j;
                int dlt = q - key;
                bool ok = (key >= 0) && (key < LL) && (dlt != 0) &&
                          (dlt <= WIN) && (dlt >= -WIN);
                float sv = ok ? Ps[r][j] : -INFINITY;
                mx = fmaxf(mx, sv);
            }
            float alpha = __expf(mold - mx);
            float lsum = rowl[r] * alpha;
            #pragma unroll
            for (int j = 0; j < 32; j++) {
                int key = kc + j;
                int dlt = q - key;
                bool ok = (key >= 0) && (key < LL) && (dlt != 0) &&
                          (dlt <= WIN) && (dlt >= -WIN);
                float p = ok ? __expf(Ps[r][j] - mx) : 0.f;
                lsum += p;
                Ps[r][j] = p;
            }
            rowm[r] = mx; rowl[r] = lsum; rowa[r] = alpha;
        }
        __syncthreads();

        // --- rescale accumulators, then O += P @ V ---
        {
            float al[4];
            #pragma unroll
            for (int i = 0; i < 4; i++) al[i] = rowa[ty * 4 + i];
            #pragma unroll
            for (int i = 0; i < 4; i++)
                #pragma unroll
                for (int j = 0; j < 4; j++) oacc[i][j] *= al[i];

            #pragma unroll
            for (int j = 0; j < 32; j++) {
                float p[4];
                #pragma unroll
                for (int i = 0; i < 4; i++) p[i] = Ps[ty * 4 + i][j];
                float4 vv = *reinterpret_cast<const float4*>(&Vs[j][tx * 4]);
                #pragma unroll
                for (int i = 0; i < 4; i++) {
                    oacc[i][0] += p[i] * vv.x;
                    oacc[i][1] += p[i] * vv.y;
                    oacc[i][2] += p[i] * vv.z;
                    oacc[i][3] += p[i] * vv.w;
                }
            }
        }
        __syncthreads();   // protect Ks/Vs/Ps before next chunk
    }

    // Epilogue: normalize and write O in [B,L,H*D] layout
    #pragma unroll
    for (int i = 0; i < 4; i++) {
        int r = ty * 4 + i;
        float inv = 1.f / rowl[r];
        float4 o;
        o.x = oacc[i][0] * inv;
        o.y = oacc[i][1] * inv;
        o.z = oacc[i][2] * inv;
        o.w = oacc[i][3] * inv;
        size_t off = (((size_t)(b * LL + q0 + r)) * HH + h) * DD + tx * 4;
        *reinterpret_cast<float4*>(&g_O[off]) = o;
    }
}

// ---------------------------------------------------------------------------
// Kernel 3: output projection GEMM
//   out[i,f] = sum_e O[i,e]*Wout[f,e] + bout[f]
// ---------------------------------------------------------------------------
__global__ __launch_bounds__(256) void out_gemm(
    const float* __restrict__ w,      // [512,512]
    const float* __restrict__ bias,   // [512]
    float* __restrict__ out)          // [8192,512]
{
    __shared__ float As[16][64];
    __shared__ float Bs[16][64];

    const int bn = blockIdx.x;     // 0..7
    const int bm = blockIdx.y;     // 0..127
    const int tid = threadIdx.x;
    const int tx = tid & 15;
    const int ty = tid >> 4;
    const int m0 = bm * 64;
    const int n0 = bn * 64;

    float acc[4][4];
    #pragma unroll
    for (int i = 0; i < 4; i++)
        #pragma unroll
        for (int j = 0; j < 4; j++) acc[i][j] = 0.f;

    const int lm = tid >> 2;
    const int lk = (tid & 3) * 4;

    for (int k0 = 0; k0 < EE; k0 += 16) {
        float4 av = *reinterpret_cast<const float4*>(&g_O[(size_t)(m0 + lm) * EE + k0 + lk]);
        float4 bv = *reinterpret_cast<const float4*>(&w[(size_t)(n0 + lm) * EE + k0 + lk]);
        As[lk + 0][lm] = av.x; As[lk + 1][lm] = av.y;
        As[lk + 2][lm] = av.z; As[lk + 3][lm] = av.w;
        Bs[lk + 0][lm] = bv.x; Bs[lk + 1][lm] = bv.y;
        Bs[lk + 2][lm] = bv.z; Bs[lk + 3][lm] = bv.w;
        __syncthreads();

        #pragma unroll
        for (int k = 0; k < 16; k++) {
            float4 a = *reinterpret_cast<const float4*>(&As[k][ty * 4]);
            float4 b = *reinterpret_cast<const float4*>(&Bs[k][tx * 4]);
            float ar[4] = {a.x, a.y, a.z, a.w};
            float br[4] = {b.x, b.y, b.z, b.w};
            #pragma unroll
            for (int i = 0; i < 4; i++)
                #pragma unroll
                for (int j = 0; j < 4; j++)
                    acc[i][j] += ar[i] * br[j];
        }
        __syncthreads();
    }

    float bsv[4];
    #pragma unroll
    for (int j = 0; j < 4; j++) bsv[j] = bias[n0 + tx * 4 + j];

    #pragma unroll
    for (int i = 0; i < 4; i++) {
        int row = m0 + ty * 4 + i;
        float4 o;
        o.x = acc[i][0] + bsv[0];
        o.y = acc[i][1] + bsv[1];
        o.z = acc[i][2] + bsv[2];
        o.w = acc[i][3] + bsv[3];
        *reinterpret_cast<float4*>(&out[(size_t)row * EE + n0 + tx * 4]) = o;
    }
}

// ---------------------------------------------------------------------------
// Entry point
// ---------------------------------------------------------------------------
extern "C" void kernel_launch(void* const* d_in, const int* in_sizes, int n_in,
                              void* d_out, int out_size)
{
    const float* x    = (const float*)d_in[0];   // [B,L,E]
    const float* wqkv = (const float*)d_in[1];   // [3E,E]
    const float* bqkv = (const float*)d_in[2];   // [3E]
    const float* wout = (const float*)d_in[3];   // [E,E]
    const float* bout = (const float*)d_in[4];   // [E]
    float* out = (float*)d_out;                  // [B,L,E]

    (void)in_sizes; (void)n_in; (void)out_size;

    dim3 g1(QKVN / 64, NTOK / 64);     // (24, 128)
    qkv_gemm<<<g1, 256>>>(x, wqkv, bqkv);

    dim3 g2(LL / 64, HH, BB);          // (64, 8, 2)
    attn_kernel<<<g2, 256>>>();

    dim3 g3(EE / 64, NTOK / 64);       // (8, 128)
    out_gemm<<<g3, 256>>>(wout, bout, out);
}

// round 3
// speedup vs baseline: 1.9923x; 1.9923x over previous
#include <cuda_runtime.h>
#include <cuda_bf16.h>
#include <cstdint>
#include <math.h>

// Problem constants
#define BB   2
#define LL   4096
#define EE   512
#define HH   8
#define DD   64
#define WIN  128
#define NTOK (BB*LL)          // 8192
#define QKVN (3*EE)           // 1536

// ---------------------------------------------------------------------------
// Device scratch
// ---------------------------------------------------------------------------
__device__ float g_Q[BB*HH*LL*DD];
__device__ float g_K[BB*HH*LL*DD];
__device__ float g_V[BB*HH*LL*DD];
__device__ float g_O[BB*LL*EE];

// ---------------------------------------------------------------------------
// Helpers
// ---------------------------------------------------------------------------
__device__ __forceinline__ uint32_t f2tf32(float x) {
    uint32_t r;
    asm("cvt.rna.tf32.f32 %0, %1;" : "=r"(r) : "f"(x));
    return r;
}

__device__ __forceinline__ void mma_tf32(float* d, const uint32_t* a,
                                         const uint32_t* b) {
    asm volatile(
        "mma.sync.aligned.m16n8k8.row.col.f32.tf32.tf32.f32 "
        "{%0,%1,%2,%3}, {%4,%5,%6,%7}, {%8,%9}, {%0,%1,%2,%3};"
        : "+f"(d[0]), "+f"(d[1]), "+f"(d[2]), "+f"(d[3])
        : "r"(a[0]), "r"(a[1]), "r"(a[2]), "r"(a[3]),
          "r"(b[0]), "r"(b[1]));
}

// ---------------------------------------------------------------------------
// tf32 mma.sync GEMM: C[M,N] = A[M,K] @ Bw[N,K]^T + bias, K = 512
//   CTA tile 128x128, BK=32, 8 warps (2x4), warp tile 64x32.
//   Fragment layout (m16n8k8): g = lane>>2, c = lane&3
//     A: a0=(g,c) a1=(g+8,c) a2=(g,c+4) a3=(g+8,c+4)
//     B: b0=(k=c,n=g) b1=(k=c+4,n=g)
//     C: c0=(g,2c) c1=(g,2c+1) c2=(g+8,2c) c3=(g+8,2c+1)
//   Smem pad = 36 floats/row: fragment address ≡ 4g+c (mod 32) -> no conflicts.
//   mode 0: qkv projection (scatter to g_Q/g_K/g_V, fold 0.125 into Q)
//   mode 1: out projection (write outp + bias)
// ---------------------------------------------------------------------------
#define SPAD 36

__global__ __launch_bounds__(256) void tf32_gemm(
    const float* __restrict__ Ain, const float* __restrict__ Bw,
    const float* __restrict__ bias, float* __restrict__ outp, int mode)
{
    __shared__ float As[128 * SPAD];
    __shared__ float Bs[128 * SPAD];

    const int tid = threadIdx.x;
    const int m0 = blockIdx.y * 128;
    const int n0 = blockIdx.x * 128;
    const float* A = (mode == 1) ? g_O : Ain;

    const int w    = tid >> 5;
    const int lane = tid & 31;
    const int g    = lane >> 2;
    const int c    = lane & 3;
    const int rm   = (w >> 2) * 64;     // warp row base (0 / 64)
    const int cn   = (w & 3) * 32;      // warp col base (0/32/64/96)

    float acc[4][4][4];
    #pragma unroll
    for (int mi = 0; mi < 4; mi++)
        #pragma unroll
        for (int ni = 0; ni < 4; ni++)
            #pragma unroll
            for (int r = 0; r < 4; r++) acc[mi][ni][r] = 0.f;

    const int lrow = tid >> 3;           // 0..31 within each 256-thread pass
    const int lk4  = (tid & 7) * 4;      // 0,4,...,28

    for (int kc = 0; kc < 16; kc++) {
        // ---- stage 128x32 A and B chunks (tf32-rounded) ----
        #pragma unroll
        for (int i = 0; i < 4; i++) {
            int row = lrow + i * 32;
            float4 va = *reinterpret_cast<const float4*>(
                A + (size_t)(m0 + row) * EE + kc * 32 + lk4);
            float4 vb = *reinterpret_cast<const float4*>(
                Bw + (size_t)(n0 + row) * EE + kc * 32 + lk4);
            float* ad = As + row * SPAD + lk4;
            ad[0] = __uint_as_float(f2tf32(va.x));
            ad[1] = __uint_as_float(f2tf32(va.y));
            ad[2] = __uint_as_float(f2tf32(va.z));
            ad[3] = __uint_as_float(f2tf32(va.w));
            float* bd = Bs + row * SPAD + lk4;
            bd[0] = __uint_as_float(f2tf32(vb.x));
            bd[1] = __uint_as_float(f2tf32(vb.y));
            bd[2] = __uint_as_float(f2tf32(vb.z));
            bd[3] = __uint_as_float(f2tf32(vb.w));
        }
        __syncthreads();

        // ---- 4 k-steps of 8 ----
        #pragma unroll
        for (int ks = 0; ks < 4; ks++) {
            uint32_t af[4][4], bf[4][2];
            #pragma unroll
            for (int mi = 0; mi < 4; mi++) {
                const float* base = As + (rm + mi * 16 + g) * SPAD + ks * 8;
                af[mi][0] = __float_as_uint(base[c]);
                af[mi][1] = __float_as_uint(base[8 * SPAD + c]);
                af[mi][2] = __float_as_uint(base[c + 4]);
                af[mi][3] = __float_as_uint(base[8 * SPAD + c + 4]);
            }
            #pragma unroll
            for (int ni = 0; ni < 4; ni++) {
                const float* base = Bs + (cn + ni * 8 + g) * SPAD + ks * 8;
                bf[ni][0] = __float_as_uint(base[c]);
                bf[ni][1] = __float_as_uint(base[c + 4]);
            }
            #pragma unroll
            for (int mi = 0; mi < 4; mi++)
                #pragma unroll
                for (int ni = 0; ni < 4; ni++)
                    mma_tf32(acc[mi][ni], af[mi], bf[ni]);
        }
        __syncthreads();
    }

    // ---- epilogue ----
    float bv[4][2];
    #pragma unroll
    for (int ni = 0; ni < 4; ni++) {
        int gn = n0 + cn + ni * 8 + 2 * c;
        bv[ni][0] = bias[gn];
        bv[ni][1] = bias[gn + 1];
    }

    if (mode == 0) {
        // column block (32 wide, 32-aligned) sits inside one (sel, head) stripe
        const int gnb = n0 + cn;
        const int sel = gnb >> 9;
        const int h   = (gnb >> 6) & 7;
        const float scale = (sel == 0) ? 0.125f : 1.0f;
        float* dst = (sel == 0) ? g_Q : (sel == 1) ? g_K : g_V;
        #pragma unroll
        for (int mi = 0; mi < 4; mi++) {
            #pragma unroll
            for (int half = 0; half < 2; half++) {
                int gm  = m0 + rm + mi * 16 + g + half * 8;
                int bat = gm >> 12;
                int l   = gm & (LL - 1);
                size_t rowbase = (((size_t)(bat * HH + h) * LL) + l) * DD;
                #pragma unroll
                for (int ni = 0; ni < 4; ni++) {
                    int gn = n0 + cn + ni * 8 + 2 * c;
                    int d  = gn & 63;
                    float2 o;
                    o.x = (acc[mi][ni][half * 2 + 0] + bv[ni][0]) * scale;
                    o.y = (acc[mi][ni][half * 2 + 1] + bv[ni][1]) * scale;
                    *reinterpret_cast<float2*>(dst + rowbase + d) = o;
                }
            }
        }
    } else {
        #pragma unroll
        for (int mi = 0; mi < 4; mi++) {
            #pragma unroll
            for (int half = 0; half < 2; half++) {
                int gm = m0 + rm + mi * 16 + g + half * 8;
                #pragma unroll
                for (int ni = 0; ni < 4; ni++) {
                    int gn = n0 + cn + ni * 8 + 2 * c;
                    float2 o;
                    o.x = acc[mi][ni][half * 2 + 0] + bv[ni][0];
                    o.y = acc[mi][ni][half * 2 + 1] + bv[ni][1];
                    *reinterpret_cast<float2*>(outp + (size_t)gm * EE + gn) = o;
                }
            }
        }
    }
}

// ---------------------------------------------------------------------------
// Kernel 2: banded flash attention (scalar, unchanged — known good)
// ---------------------------------------------------------------------------
__global__ __launch_bounds__(256) void attn_kernel()
{
    __shared__ float Qs[64][64];
    __shared__ float Ks[64][32];
    __shared__ float Vs[32][64];
    __shared__ float Ps[64][33];
    __shared__ float rowm[64], rowl[64], rowa[64];

    const int q0 = blockIdx.x * 64;
    const int h  = blockIdx.y;
    const int b  = blockIdx.z;
    const int tid = threadIdx.x;
    const int tx = tid & 15;
    const int ty = tid >> 4;

    const size_t head_off = ((size_t)(b * HH + h) * LL) * DD;
    const float* Qg = g_Q + head_off;
    const float* Kg = g_K + head_off;
    const float* Vg = g_V + head_off;

    #pragma unroll
    for (int it = 0; it < 16; it++) {
        int idx = tid + it * 256;
        int r = idx >> 6, d = idx & 63;
        Qs[d][r] = Qg[(size_t)(q0 + r) * DD + d];
    }
    if (tid < 64) { rowm[tid] = -1e30f; rowl[tid] = 0.f; }

    float oacc[4][4];
    #pragma unroll
    for (int i = 0; i < 4; i++)
        #pragma unroll
        for (int j = 0; j < 4; j++) oacc[i][j] = 0.f;

    __syncthreads();

    const int kstart = q0 - WIN;

    for (int cch = 0; cch < 10; cch++) {
        int kc = kstart + cch * 32;
        if (kc + 32 <= 0 || kc >= LL) continue;

        {
            int dd = (tid & 15) * 4;
            #pragma unroll
            for (int p = 0; p < 2; p++) {
                int j = (tid >> 4) + p * 16;
                int key = kc + j;
                int kk = min(max(key, 0), LL - 1);
                float4 kv = *reinterpret_cast<const float4*>(&Kg[(size_t)kk * DD + dd]);
                Ks[dd + 0][j] = kv.x; Ks[dd + 1][j] = kv.y;
                Ks[dd + 2][j] = kv.z; Ks[dd + 3][j] = kv.w;
                float4 vv = *reinterpret_cast<const float4*>(&Vg[(size_t)kk * DD + dd]);
                *reinterpret_cast<float4*>(&Vs[j][dd]) = vv;
            }
        }
        __syncthreads();

        {
            float s[4][2];
            #pragma unroll
            for (int i = 0; i < 4; i++) { s[i][0] = 0.f; s[i][1] = 0.f; }
            #pragma unroll
            for (int d = 0; d < 64; d++) {
                float4 a = *reinterpret_cast<const float4*>(&Qs[d][ty * 4]);
                float ar[4] = {a.x, a.y, a.z, a.w};
                float b0 = Ks[d][tx * 2];
                float b1 = Ks[d][tx * 2 + 1];
                #pragma unroll
                for (int i = 0; i < 4; i++) {
                    s[i][0] += ar[i] * b0;
                    s[i][1] += ar[i] * b1;
                }
            }
            #pragma unroll
            for (int i = 0; i < 4; i++) {
                Ps[ty * 4 + i][tx * 2 + 0] = s[i][0];
                Ps[ty * 4 + i][tx * 2 + 1] = s[i][1];
            }
        }
        __syncthreads();

        if (tid < 64) {
            int r = tid;
            int q = q0 + r;
            float mold = rowm[r];
            float mx = mold;
            #pragma unroll
            for (int j = 0; j < 32; j++) {
                int key = kc + j;
                int dlt = q - key;
                bool ok = (key >= 0) && (key < LL) && (dlt != 0) &&
                          (dlt <= WIN) && (dlt >= -WIN);
                float sv = ok ? Ps[r][j] : -INFINITY;
                mx = fmaxf(mx, sv);
            }
            float alpha = __expf(mold - mx);
            float lsum = rowl[r] * alpha;
            #pragma unroll
            for (int j = 0; j < 32; j++) {
                int key = kc + j;
                int dlt = q - key;
                bool ok = (key >= 0) && (key < LL) && (dlt != 0) &&
                          (dlt <= WIN) && (dlt >= -WIN);
                float p = ok ? __expf(Ps[r][j] - mx) : 0.f;
                lsum += p;
                Ps[r][j] = p;
            }
            rowm[r] = mx; rowl[r] = lsum; rowa[r] = alpha;
        }
        __syncthreads();

        {
            float al[4];
            #pragma unroll
            for (int i = 0; i < 4; i++) al[i] = rowa[ty * 4 + i];
            #pragma unroll
            for (int i = 0; i < 4; i++)
                #pragma unroll
                for (int j = 0; j < 4; j++) oacc[i][j] *= al[i];

            #pragma unroll
            for (int j = 0; j < 32; j++) {
                float p[4];
                #pragma unroll
                for (int i = 0; i < 4; i++) p[i] = Ps[ty * 4 + i][j];
                float4 vv = *reinterpret_cast<const float4*>(&Vs[j][tx * 4]);
                #pragma unroll
                for (int i = 0; i < 4; i++) {
                    oacc[i][0] += p[i] * vv.x;
                    oacc[i][1] += p[i] * vv.y;
                    oacc[i][2] += p[i] * vv.z;
                    oacc[i][3] += p[i] * vv.w;
                }
            }
        }
        __syncthreads();
    }

    #pragma unroll
    for (int i = 0; i < 4; i++) {
        int r = ty * 4 + i;
        float inv = 1.f / rowl[r];
        float4 o;
        o.x = oacc[i][0] * inv;
        o.y = oacc[i][1] * inv;
        o.z = oacc[i][2] * inv;
        o.w = oacc[i][3] * inv;
        size_t off = (((size_t)(b * LL + q0 + r)) * HH + h) * DD + tx * 4;
        *reinterpret_cast<float4*>(&g_O[off]) = o;
    }
}

// ---------------------------------------------------------------------------
// Entry point
// ---------------------------------------------------------------------------
extern "C" void kernel_launch(void* const* d_in, const int* in_sizes, int n_in,
                              void* d_out, int out_size)
{
    const float* x    = (const float*)d_in[0];   // [B,L,E]
    const float* wqkv = (const float*)d_in[1];   // [3E,E]
    const float* bqkv = (const float*)d_in[2];   // [3E]
    const float* wout = (const float*)d_in[3];   // [E,E]
    const float* bout = (const float*)d_in[4];   // [E]
    float* out = (float*)d_out;                  // [B,L,E]

    (void)in_sizes; (void)n_in; (void)out_size;

    // QKV projection: M=8192, N=1536
    tf32_gemm<<<dim3(QKVN / 128, NTOK / 128), 256>>>(x, wqkv, bqkv, nullptr, 0);

    // banded attention
    dim3 g2(LL / 64, HH, BB);
    attn_kernel<<<g2, 256>>>();

    // out projection: M=8192, N=512
    tf32_gemm<<<dim3(EE / 128, NTOK / 128), 256>>>(nullptr, wout, bout, out, 1);
}

// round 5
// speedup vs baseline: 2.6060x; 1.3081x over previous
#include <cuda_runtime.h>
#include <cuda_bf16.h>
#include <cstdint>
#include <math.h>

// Problem constants
#define BB   2
#define LL   4096
#define EE   512
#define HH   8
#define DD   64
#define WIN  128
#define NTOK (BB*LL)          // 8192
#define QKVN (3*EE)           // 1536

// ---------------------------------------------------------------------------
// Device scratch
// ---------------------------------------------------------------------------
__device__ float g_Q[BB*HH*LL*DD];
__device__ float g_K[BB*HH*LL*DD];
__device__ float g_V[BB*HH*LL*DD];
__device__ float g_O[BB*LL*EE];

// ---------------------------------------------------------------------------
// Helpers
// ---------------------------------------------------------------------------
__device__ __forceinline__ uint32_t f2tf32(float x) {
    uint32_t r;
    asm("cvt.rna.tf32.f32 %0, %1;" : "=r"(r) : "f"(x));
    return r;
}
__device__ __forceinline__ void split_tf32(float x, uint32_t& hi, uint32_t& lo) {
    uint32_t h = f2tf32(x);
    hi = h;
    lo = f2tf32(x - __uint_as_float(h));
}

__device__ __forceinline__ void mma_tf32(float* d, const uint32_t* a,
                                         const uint32_t* b) {
    asm volatile(
        "mma.sync.aligned.m16n8k8.row.col.f32.tf32.tf32.f32 "
        "{%0,%1,%2,%3}, {%4,%5,%6,%7}, {%8,%9}, {%0,%1,%2,%3};"
        : "+f"(d[0]), "+f"(d[1]), "+f"(d[2]), "+f"(d[3])
        : "r"(a[0]), "r"(a[1]), "r"(a[2]), "r"(a[3]),
          "r"(b[0]), "r"(b[1]));
}

// ---------------------------------------------------------------------------
// tf32 mma.sync GEMM (unchanged from round 3 — known good)
// ---------------------------------------------------------------------------
#define SPAD 36

__global__ __launch_bounds__(256) void tf32_gemm(
    const float* __restrict__ Ain, const float* __restrict__ Bw,
    const float* __restrict__ bias, float* __restrict__ outp, int mode)
{
    __shared__ float As[128 * SPAD];
    __shared__ float Bs[128 * SPAD];

    const int tid = threadIdx.x;
    const int m0 = blockIdx.y * 128;
    const int n0 = blockIdx.x * 128;
    const float* A = (mode == 1) ? g_O : Ain;

    const int w    = tid >> 5;
    const int lane = tid & 31;
    const int g    = lane >> 2;
    const int c    = lane & 3;
    const int rm   = (w >> 2) * 64;
    const int cn   = (w & 3) * 32;

    float acc[4][4][4];
    #pragma unroll
    for (int mi = 0; mi < 4; mi++)
        #pragma unroll
        for (int ni = 0; ni < 4; ni++)
            #pragma unroll
            for (int r = 0; r < 4; r++) acc[mi][ni][r] = 0.f;

    const int lrow = tid >> 3;
    const int lk4  = (tid & 7) * 4;

    for (int kc = 0; kc < 16; kc++) {
        #pragma unroll
        for (int i = 0; i < 4; i++) {
            int row = lrow + i * 32;
            float4 va = *reinterpret_cast<const float4*>(
                A + (size_t)(m0 + row) * EE + kc * 32 + lk4);
            float4 vb = *reinterpret_cast<const float4*>(
                Bw + (size_t)(n0 + row) * EE + kc * 32 + lk4);
            float* ad = As + row * SPAD + lk4;
            ad[0] = __uint_as_float(f2tf32(va.x));
            ad[1] = __uint_as_float(f2tf32(va.y));
            ad[2] = __uint_as_float(f2tf32(va.z));
            ad[3] = __uint_as_float(f2tf32(va.w));
            float* bd = Bs + row * SPAD + lk4;
            bd[0] = __uint_as_float(f2tf32(vb.x));
            bd[1] = __uint_as_float(f2tf32(vb.y));
            bd[2] = __uint_as_float(f2tf32(vb.z));
            bd[3] = __uint_as_float(f2tf32(vb.w));
        }
        __syncthreads();

        #pragma unroll
        for (int ks = 0; ks < 4; ks++) {
            uint32_t af[4][4], bf[4][2];
            #pragma unroll
            for (int mi = 0; mi < 4; mi++) {
                const float* base = As + (rm + mi * 16 + g) * SPAD + ks * 8;
                af[mi][0] = __float_as_uint(base[c]);
                af[mi][1] = __float_as_uint(base[8 * SPAD + c]);
                af[mi][2] = __float_as_uint(base[c + 4]);
                af[mi][3] = __float_as_uint(base[8 * SPAD + c + 4]);
            }
            #pragma unroll
            for (int ni = 0; ni < 4; ni++) {
                const float* base = Bs + (cn + ni * 8 + g) * SPAD + ks * 8;
                bf[ni][0] = __float_as_uint(base[c]);
                bf[ni][1] = __float_as_uint(base[c + 4]);
            }
            #pragma unroll
            for (int mi = 0; mi < 4; mi++)
                #pragma unroll
                for (int ni = 0; ni < 4; ni++)
                    mma_tf32(acc[mi][ni], af[mi], bf[ni]);
        }
        __syncthreads();
    }

    float bv[4][2];
    #pragma unroll
    for (int ni = 0; ni < 4; ni++) {
        int gn = n0 + cn + ni * 8 + 2 * c;
        bv[ni][0] = bias[gn];
        bv[ni][1] = bias[gn + 1];
    }

    if (mode == 0) {
        const int gnb = n0 + cn;
        const int sel = gnb >> 9;
        const int h   = (gnb >> 6) & 7;
        const float scale = (sel == 0) ? 0.125f : 1.0f;
        float* dst = (sel == 0) ? g_Q : (sel == 1) ? g_K : g_V;
        #pragma unroll
        for (int mi = 0; mi < 4; mi++) {
            #pragma unroll
            for (int half = 0; half < 2; half++) {
                int gm  = m0 + rm + mi * 16 + g + half * 8;
                int bat = gm >> 12;
                int l   = gm & (LL - 1);
                size_t rowbase = (((size_t)(bat * HH + h) * LL) + l) * DD;
                #pragma unroll
                for (int ni = 0; ni < 4; ni++) {
                    int gn = n0 + cn + ni * 8 + 2 * c;
                    int d  = gn & 63;
                    float2 o;
                    o.x = (acc[mi][ni][half * 2 + 0] + bv[ni][0]) * scale;
                    o.y = (acc[mi][ni][half * 2 + 1] + bv[ni][1]) * scale;
                    *reinterpret_cast<float2*>(dst + rowbase + d) = o;
                }
            }
        }
    } else {
        #pragma unroll
        for (int mi = 0; mi < 4; mi++) {
            #pragma unroll
            for (int half = 0; half < 2; half++) {
                int gm = m0 + rm + mi * 16 + g + half * 8;
                #pragma unroll
                for (int ni = 0; ni < 4; ni++) {
                    int gn = n0 + cn + ni * 8 + 2 * c;
                    float2 o;
                    o.x = acc[mi][ni][half * 2 + 0] + bv[ni][0];
                    o.y = acc[mi][ni][half * 2 + 1] + bv[ni][1];
                    *reinterpret_cast<float2*>(outp + (size_t)gm * EE + gn) = o;
                }
            }
        }
    }
}

// ---------------------------------------------------------------------------
// Banded flash attention with split-tf32 (3xTF32) tensor-core GEMMs.
//   Block: 128 threads (4 warps), 64-query tile, key chunks of 64.
//   Warp w owns query rows [16w, 16w+16).
//   Smem pad 68: fragment LDS addresses ≡ 4g+c (mod 32) -> conflict-free.
// ---------------------------------------------------------------------------
#define APAD 68
#define ATTN_SMEM (4 * 64 * APAD * 4)

__global__ __launch_bounds__(128) void attn_mma()
{
    extern __shared__ float sm[];
    float* Qs = sm;                  // [64][APAD]  (q, d)
    float* Ks = sm + 64 * APAD;      // [64][APAD]  (key, d)
    float* Vs = sm + 2 * 64 * APAD;  // [64][APAD]  (key, d)
    float* Ps = sm + 3 * 64 * APAD;  // [64][APAD]  (q, key-local)

    const int q0 = blockIdx.x * 64;
    const int h  = blockIdx.y;
    const int b  = blockIdx.z;
    const int tid  = threadIdx.x;
    const int w    = tid >> 5;
    const int lane = tid & 31;
    const int g    = lane >> 2;
    const int c    = lane & 3;

    const size_t head_off = ((size_t)(b * HH + h) * LL) * DD;
    const float* Qg = g_Q + head_off;
    const float* Kg = g_K + head_off;
    const float* Vg = g_V + head_off;

    // Load Q tile [64][64] (row-major q x d)
    #pragma unroll
    for (int i = 0; i < 8; i++) {
        int u = tid + i * 128;           // 0..1023 float4 units
        int row = u >> 4;
        int col = (u & 15) * 4;
        float4 v = *reinterpret_cast<const float4*>(&Qg[(size_t)(q0 + row) * DD + col]);
        *reinterpret_cast<float4*>(&Qs[row * APAD + col]) = v;
    }

    float om[2] = {-1e30f, -1e30f};      // running max (row g, row g+8)
    float ol[2] = {0.f, 0.f};            // running sum
    float oacc[8][4];
    #pragma unroll
    for (int nt = 0; nt < 8; nt++)
        #pragma unroll
        for (int r = 0; r < 4; r++) oacc[nt][r] = 0.f;

    __syncthreads();

    const int row_lo = 16 * w + g;       // global-q offsets within tile
    const int q_lo = q0 + row_lo;
    const int q_hi = q_lo + 8;

    for (int ch = 0; ch < 5; ch++) {
        const int kc = q0 - 2 * WIN / 2 - 64 + (ch + 1) * 64 - 64; // q0-128+ch*64
        const int kcc = q0 - 128 + ch * 64;
        if (kcc + 64 <= 0 || kcc >= LL) continue;

        // ---- load K,V chunk [64][64] ----
        #pragma unroll
        for (int i = 0; i < 8; i++) {
            int u = tid + i * 128;
            int row = u >> 4;
            int col = (u & 15) * 4;
            int key = kcc + row;
            int kk = min(max(key, 0), LL - 1);
            float4 kv = *reinterpret_cast<const float4*>(&Kg[(size_t)kk * DD + col]);
            *reinterpret_cast<float4*>(&Ks[row * APAD + col]) = kv;
            float4 vv = *reinterpret_cast<const float4*>(&Vg[(size_t)kk * DD + col]);
            *reinterpret_cast<float4*>(&Vs[row * APAD + col]) = vv;
        }
        __syncthreads();

        // ---- scores S[16][64] per warp via split-tf32 MMA ----
        float sacc[8][4];
        #pragma unroll
        for (int nt = 0; nt < 8; nt++)
            #pragma unroll
            for (int r = 0; r < 4; r++) sacc[nt][r] = 0.f;

        #pragma unroll
        for (int ks = 0; ks < 8; ks++) {
            const float* ab = Qs + row_lo * APAD + ks * 8;
            uint32_t ah[4], al[4];
            split_tf32(ab[c],               ah[0], al[0]);
            split_tf32(ab[8 * APAD + c],    ah[1], al[1]);
            split_tf32(ab[c + 4],           ah[2], al[2]);
            split_tf32(ab[8 * APAD + c + 4],ah[3], al[3]);
            #pragma unroll
            for (int nt = 0; nt < 8; nt++) {
                const float* bb = Ks + (nt * 8 + g) * APAD + ks * 8;
                uint32_t bh[2], bl[2];
                split_tf32(bb[c],     bh[0], bl[0]);
                split_tf32(bb[c + 4], bh[1], bl[1]);
                mma_tf32(sacc[nt], ah, bh);
                mma_tf32(sacc[nt], al, bh);
                mma_tf32(sacc[nt], ah, bl);
            }
        }

        // ---- mask ----
        #pragma unroll
        for (int nt = 0; nt < 8; nt++) {
            #pragma unroll
            for (int r = 0; r < 4; r++) {
                int key = kcc + nt * 8 + 2 * c + (r & 1);
                int q   = (r >> 1) ? q_hi : q_lo;
                int dlt = q - key;
                bool ok = (key >= 0) && (key < LL) && (dlt != 0) &&
                          (dlt <= WIN) && (dlt >= -WIN);
                if (!ok) sacc[nt][r] = -1e30f;
            }
        }

        // ---- online softmax (rows g and g+8, replicated in quad) ----
        float mx0 = -1e30f, mx1 = -1e30f;
        #pragma unroll
        for (int nt = 0; nt < 8; nt++) {
            mx0 = fmaxf(mx0, fmaxf(sacc[nt][0], sacc[nt][1]));
            mx1 = fmaxf(mx1, fmaxf(sacc[nt][2], sacc[nt][3]));
        }
        mx0 = fmaxf(mx0, __shfl_xor_sync(0xffffffffu, mx0, 1));
        mx0 = fmaxf(mx0, __shfl_xor_sync(0xffffffffu, mx0, 2));
        mx1 = fmaxf(mx1, __shfl_xor_sync(0xffffffffu, mx1, 1));
        mx1 = fmaxf(mx1, __shfl_xor_sync(0xffffffffu, mx1, 2));

        float m0n = fmaxf(om[0], mx0);
        float m1n = fmaxf(om[1], mx1);
        float alpha0 = __expf(om[0] - m0n);
        float alpha1 = __expf(om[1] - m1n);

        float sum0 = 0.f, sum1 = 0.f;
        #pragma unroll
        for (int nt = 0; nt < 8; nt++) {
            float p0 = __expf(sacc[nt][0] - m0n);
            float p1 = __expf(sacc[nt][1] - m0n);
            float p2 = __expf(sacc[nt][2] - m1n);
            float p3 = __expf(sacc[nt][3] - m1n);
            sum0 += p0 + p1;
            sum1 += p2 + p3;
            *reinterpret_cast<float2*>(&Ps[row_lo * APAD + nt * 8 + 2 * c]) =
                make_float2(p0, p1);
            *reinterpret_cast<float2*>(&Ps[(row_lo + 8) * APAD + nt * 8 + 2 * c]) =
                make_float2(p2, p3);
        }
        sum0 += __shfl_xor_sync(0xffffffffu, sum0, 1);
        sum0 += __shfl_xor_sync(0xffffffffu, sum0, 2);
        sum1 += __shfl_xor_sync(0xffffffffu, sum1, 1);
        sum1 += __shfl_xor_sync(0xffffffffu, sum1, 2);

        ol[0] = ol[0] * alpha0 + sum0;
        ol[1] = ol[1] * alpha1 + sum1;
        om[0] = m0n;
        om[1] = m1n;

        #pragma unroll
        for (int nt = 0; nt < 8; nt++) {
            oacc[nt][0] *= alpha0;
            oacc[nt][1] *= alpha0;
            oacc[nt][2] *= alpha1;
            oacc[nt][3] *= alpha1;
        }
        __syncwarp();

        // ---- O += P @ V (split-tf32) ----
        #pragma unroll
        for (int ks = 0; ks < 8; ks++) {
            const float* pb = Ps + row_lo * APAD + ks * 8;
            uint32_t ah[4], al[4];
            split_tf32(pb[c],                ah[0], al[0]);
            split_tf32(pb[8 * APAD + c],     ah[1], al[1]);
            split_tf32(pb[c + 4],            ah[2], al[2]);
            split_tf32(pb[8 * APAD + c + 4], ah[3], al[3]);
            #pragma unroll
            for (int nt = 0; nt < 8; nt++) {
                uint32_t bh[2], bl[2];
                split_tf32(Vs[(ks * 8 + c) * APAD + nt * 8 + g],     bh[0], bl[0]);
                split_tf32(Vs[(ks * 8 + c + 4) * APAD + nt * 8 + g], bh[1], bl[1]);
                mma_tf32(oacc[nt], ah, bh);
                mma_tf32(oacc[nt], al, bh);
                mma_tf32(oacc[nt], ah, bl);
            }
        }
        __syncthreads();
        (void)kc;
    }

    // ---- epilogue: normalize, write O[b][l][h*64+d] ----
    const float inv0 = 1.f / ol[0];
    const float inv1 = 1.f / ol[1];
    const size_t base_lo = ((size_t)(b * LL + q_lo) * HH + h) * DD;
    const size_t base_hi = ((size_t)(b * LL + q_hi) * HH + h) * DD;
    #pragma unroll
    for (int nt = 0; nt < 8; nt++) {
        int d = nt * 8 + 2 * c;
        *reinterpret_cast<float2*>(&g_O[base_lo + d]) =
            make_float2(oacc[nt][0] * inv0, oacc[nt][1] * inv0);
        *reinterpret_cast<float2*>(&g_O[base_hi + d]) =
            make_float2(oacc[nt][2] * inv1, oacc[nt][3] * inv1);
    }
}

// ---------------------------------------------------------------------------
// Entry point
// ---------------------------------------------------------------------------
extern "C" void kernel_launch(void* const* d_in, const int* in_sizes, int n_in,
                              void* d_out, int out_size)
{
    const float* x    = (const float*)d_in[0];   // [B,L,E]
    const float* wqkv = (const float*)d_in[1];   // [3E,E]
    const float* bqkv = (const float*)d_in[2];   // [3E]
    const float* wout = (const float*)d_in[3];   // [E,E]
    const float* bout = (const float*)d_in[4];   // [E]
    float* out = (float*)d_out;                  // [B,L,E]

    (void)in_sizes; (void)n_in; (void)out_size;

    cudaFuncSetAttribute(attn_mma, cudaFuncAttributeMaxDynamicSharedMemorySize,
                         ATTN_SMEM);

    // QKV projection: M=8192, N=1536
    tf32_gemm<<<dim3(QKVN / 128, NTOK / 128), 256>>>(x, wqkv, bqkv, nullptr, 0);

    // banded attention (tensor core, split tf32)
    attn_mma<<<dim3(LL / 64, HH, BB), 128, ATTN_SMEM>>>();

    // out projection: M=8192, N=512
    tf32_gemm<<<dim3(EE / 128, NTOK / 128), 256>>>(nullptr, wout, bout, out, 1);
}